// round 3
// baseline (speedup 1.0000x reference)
#include <cuda_runtime.h>
#include <math.h>

#define ADIM 6
#define ZDIM 32
#define HDIM 512
#define EDIM 1024
#define BATCH 256
#define TSTEPS 64

// output layout: h_seq[B,T,H] | z_seq | pm | ps | qm | qs (each [B,T,Z])
#define OFF_Z  (BATCH*TSTEPS*HDIM)
#define ZBLK   (BATCH*TSTEPS*ZDIM)
#define OFF_PM (OFF_Z + ZBLK)
#define OFF_PS (OFF_PM + ZBLK)
#define OFF_QM (OFF_PS + ZBLK)
#define OFF_QS (OFF_QM + ZBLK)

// scratch (device globals; no dynamic allocation allowed)
__device__ __align__(128) float g_preAZ[BATCH*TSTEPS*HDIM]; // b_az + a@W_az_a, [b][t][h]
__device__ __align__(128) float g_preHA[BATCH*TSTEPS*HDIM]; // b_ha + a@W_ha_a
__device__ __align__(128) float g_preHE[BATCH*TSTEPS*HDIM]; // b_he + e@W_he_e
__device__ __align__(128) float g_G[BATCH*3072];            // [gi(1536)|gh(1536)]
__device__ __align__(128) float g_h[BATCH*HDIM];
__device__ __align__(128) float g_x[BATCH*HDIM];
__device__ __align__(128) float g_z[BATCH*ZDIM];
__device__ __align__(128) float g_hahe[BATCH*1024];         // [ha(512)|he(512)]
__device__ __align__(128) float g_WazzT[ZDIM*HDIM];         // W_az[:, :32] transposed [k][h]
__device__ __align__(128) float g_Wha[HDIM*HDIM];           // W_ha[:, :512] packed

__device__ __forceinline__ float sigmoidf_(float x) { return 1.f / (1.f + expf(-x)); }
__device__ __forceinline__ float softplusf_(float x) {
    return fmaxf(x, 0.f) + log1pf(expf(-fabsf(x)));
}

// ---------------------------------------------------------------------------
// Pipelined SIMT GEMM core. 128 threads. Tile BM x BN, BK=16, micro TM x TN.
// Requires BM,BN in {32,64}, TM,TN in {4,8}, BM*BN == 128*TM*TN, K % 16 == 0.
// A row-major [.,lda], B row-major [BN rows, ldb] (acc = A * B^T tile).
// ---------------------------------------------------------------------------
template<int BM, int BN, int TM, int TN>
__device__ __forceinline__ void gemm_tile(
    const float* __restrict__ A, int lda,
    const float* __restrict__ B, int ldb,
    int K, float* As, float* Bs, float (&acc)[TM][TN])
{
    constexpr int LDA = BM + 4, LDB = BN + 4;
    constexpr int AREP = BM / 32, BREP = BN / 32;
    const int tid = threadIdx.x;
    const int lr = tid >> 2, lk = (tid & 3) << 2;
    const int tx = tid % (BN / TN);
    const int ty = tid / (BN / TN);

    float4 aReg[AREP], bReg[BREP];
    #pragma unroll
    for (int i = 0; i < AREP; i++)
        aReg[i] = *(const float4*)(A + (lr + 32*i)*lda + lk);
    #pragma unroll
    for (int i = 0; i < BREP; i++)
        bReg[i] = *(const float4*)(B + (lr + 32*i)*ldb + lk);

    for (int k0 = 16; k0 <= K; k0 += 16) {
        __syncthreads();
        #pragma unroll
        for (int i = 0; i < AREP; i++) {
            As[(lk+0)*LDA + lr + 32*i] = aReg[i].x;
            As[(lk+1)*LDA + lr + 32*i] = aReg[i].y;
            As[(lk+2)*LDA + lr + 32*i] = aReg[i].z;
            As[(lk+3)*LDA + lr + 32*i] = aReg[i].w;
        }
        #pragma unroll
        for (int i = 0; i < BREP; i++) {
            Bs[(lk+0)*LDB + lr + 32*i] = bReg[i].x;
            Bs[(lk+1)*LDB + lr + 32*i] = bReg[i].y;
            Bs[(lk+2)*LDB + lr + 32*i] = bReg[i].z;
            Bs[(lk+3)*LDB + lr + 32*i] = bReg[i].w;
        }
        __syncthreads();
        if (k0 < K) {
            #pragma unroll
            for (int i = 0; i < AREP; i++)
                aReg[i] = *(const float4*)(A + (lr + 32*i)*lda + k0 + lk);
            #pragma unroll
            for (int i = 0; i < BREP; i++)
                bReg[i] = *(const float4*)(B + (lr + 32*i)*ldb + k0 + lk);
        }
        #pragma unroll
        for (int kk = 0; kk < 16; kk++) {
            alignas(16) float a[TM];
            alignas(16) float b[TN];
            #pragma unroll
            for (int i = 0; i < TM/4; i++)
                *(float4*)(a + 4*i) = *(const float4*)(As + kk*LDA + ty*TM + 4*i);
            #pragma unroll
            for (int j = 0; j < TN/4; j++)
                *(float4*)(b + 4*j) = *(const float4*)(Bs + kk*LDB + tx*TN + 4*j);
            #pragma unroll
            for (int i = 0; i < TM; i++)
                #pragma unroll
                for (int j = 0; j < TN; j++)
                    acc[i][j] += a[i]*b[j];
        }
    }
}

// ---------------------------------------------------------------------------
__global__ void k_init(const float* __restrict__ prev_z, const float* __restrict__ prev_h) {
    int idx = blockIdx.x * 256 + threadIdx.x;
    if (idx < BATCH*HDIM) g_h[idx] = prev_h[idx];
    if (idx < BATCH*ZDIM) g_z[idx] = prev_z[idx];
}

// pack W_ha[:, :512] (row stride 518) and W_az[:, :32] transposed
__global__ void k_pack(const float* __restrict__ W_az, const float* __restrict__ W_ha) {
    int n = blockIdx.x;             // 0..511
    int tid = threadIdx.x;          // 256
    g_Wha[n*HDIM + tid]       = W_ha[n*(HDIM+ADIM) + tid];
    g_Wha[n*HDIM + tid + 256] = W_ha[n*(HDIM+ADIM) + tid + 256];
    if (tid < ZDIM) g_WazzT[tid*HDIM + n] = W_az[n*(ZDIM+ADIM) + tid];
}

// preAZ, preHA (action projections + biases). grid=64 (t), 256 thr
__global__ __launch_bounds__(256) void k_pre_act(
    const float* __restrict__ actions,
    const float* __restrict__ W_az, const float* __restrict__ b_az,
    const float* __restrict__ W_ha, const float* __restrict__ b_ha)
{
    __shared__ float waz[HDIM*ADIM];
    __shared__ float wha[HDIM*ADIM];
    __shared__ float baz[HDIM];
    __shared__ float bha[HDIM];
    __shared__ float act[BATCH*ADIM];
    const int t = blockIdx.x;
    const int tid = threadIdx.x;
    for (int e = tid; e < HDIM*ADIM; e += 256) {
        int h = e / ADIM, j = e - h*ADIM;
        waz[e] = W_az[h*(ZDIM+ADIM) + ZDIM + j];
        wha[e] = W_ha[h*(HDIM+ADIM) + HDIM + j];
    }
    for (int e = tid; e < HDIM; e += 256) { baz[e] = b_az[e]; bha[e] = b_ha[e]; }
    for (int e = tid; e < BATCH*ADIM; e += 256) {
        int b = e / ADIM, j = e - b*ADIM;
        act[e] = actions[(b*TSTEPS + t)*ADIM + j];
    }
    __syncthreads();
    for (int e = tid; e < BATCH*HDIM; e += 256) {
        int b = e >> 9, h = e & 511;
        float pa = baz[h], ph = bha[h];
        #pragma unroll
        for (int j = 0; j < ADIM; j++) {
            float a = act[b*ADIM + j];
            pa += a * waz[h*ADIM + j];
            ph += a * wha[h*ADIM + j];
        }
        int o = (b*TSTEPS + t)*HDIM + h;
        g_preAZ[o] = pa;
        g_preHA[o] = ph;
    }
}

// preHE = b_he + e @ W_he[:,512:].T   M=16384 (r=b*64+t), N=512, K=1024
// grid (256, 8), 128 thr
__global__ __launch_bounds__(128) void k_pre_he(
    const float* __restrict__ emb, const float* __restrict__ W_he,
    const float* __restrict__ b_he)
{
    __shared__ float As[16*68];
    __shared__ float Bs[16*68];
    const int m0 = blockIdx.x * 64;
    const int n0 = blockIdx.y * 64;
    float acc[8][4] = {};
    gemm_tile<64,64,8,4>(emb + (size_t)m0*EDIM, EDIM,
                         W_he + (size_t)n0*1536 + 512, 1536,
                         EDIM, As, Bs, acc);
    const int tx = threadIdx.x & 15, ty = threadIdx.x >> 4;
    #pragma unroll
    for (int i = 0; i < 8; i++) {
        int r = m0 + ty*8 + i, c = n0 + tx*4;
        float4 v = make_float4(acc[i][0] + b_he[c], acc[i][1] + b_he[c+1],
                               acc[i][2] + b_he[c+2], acc[i][3] + b_he[c+3]);
        *(float4*)(g_preHE + r*HDIM + c) = v;
    }
}

// x = relu(zmask @ WzzT + preAZ[t]). prologue only (t=0). grid=BATCH, 512 thr
__global__ void k_x(const float* __restrict__ dones, int t) {
    const int b = blockIdx.x, h = threadIdx.x;
    __shared__ float sz[ZDIM];
    if (h < ZDIM) sz[h] = g_z[b*ZDIM + h] * (1.f - dones[b*TSTEPS + t]);
    __syncthreads();
    float acc = g_preAZ[(b*TSTEPS + t)*HDIM + h];
    #pragma unroll
    for (int k = 0; k < ZDIM; k++) acc += sz[k] * g_WazzT[k*HDIM + h];
    g_x[b*HDIM + h] = fmaxf(acc, 0.f);
}

// G = [gi | gh]: [256, 3072], K=512. grid (4, 48), 128 thr
__global__ __launch_bounds__(128) void k_gates(
    const float* __restrict__ W_ih, const float* __restrict__ W_hh,
    const float* __restrict__ b_ih, const float* __restrict__ b_hh)
{
    __shared__ float As[16*68];
    __shared__ float Bs[16*68];
    const int m0 = blockIdx.x * 64;
    const int n0 = blockIdx.y * 64;
    const bool isI = (n0 < 1536);
    const float* A = isI ? g_x : g_h;
    const float* B = isI ? (W_ih + (size_t)n0*HDIM) : (W_hh + (size_t)(n0-1536)*HDIM);
    const float* bias = isI ? (b_ih + n0) : (b_hh + (n0-1536));
    float acc[8][4] = {};
    gemm_tile<64,64,8,4>(A + (size_t)m0*HDIM, HDIM, B, HDIM, HDIM, As, Bs, acc);
    const int tx = threadIdx.x & 15, ty = threadIdx.x >> 4;
    float b0 = bias[tx*4], b1 = bias[tx*4+1], b2 = bias[tx*4+2], b3 = bias[tx*4+3];
    #pragma unroll
    for (int i = 0; i < 8; i++) {
        float4 v = make_float4(acc[i][0]+b0, acc[i][1]+b1, acc[i][2]+b2, acc[i][3]+b3);
        *(float4*)(g_G + (m0 + ty*8 + i)*3072 + n0 + tx*4) = v;
    }
}

// GRU gate fuse. grid 512, 256 thr
__global__ void k_gru(float* __restrict__ out, int t) {
    int idx = blockIdx.x * 256 + threadIdx.x;  // 131072
    int b = idx >> 9, j = idx & 511;
    const float* Gb = g_G + b*3072;
    float r = sigmoidf_(Gb[j] + Gb[1536 + j]);
    float u = sigmoidf_(Gb[512 + j] + Gb[2048 + j]);
    float n = tanhf(Gb[1024 + j] + r * Gb[2560 + j]);
    float hp = g_h[idx];
    float h = (1.f - u)*n + u*hp;
    g_h[idx] = h;
    out[b*TSTEPS*HDIM + t*HDIM + j] = h;
}

// hahe = relu(h @ [Wha_h | Whe_h]^T + [preHA|preHE]). [256,1024], K=512.
// grid (8,16), 128 thr, tile 32x64
__global__ __launch_bounds__(128) void k_hahe(const float* __restrict__ W_he, int t) {
    __shared__ float As[16*36];
    __shared__ float Bs[16*68];
    const int m0 = blockIdx.x * 32;
    const int n0 = blockIdx.y * 64;
    const bool isHA = (n0 < 512);
    const float* B = isHA ? (g_Wha + (size_t)n0*HDIM) : (W_he + (size_t)(n0-512)*1536);
    const int ldb = isHA ? HDIM : 1536;
    const float* pre = isHA ? g_preHA : g_preHE;
    const int pc0 = isHA ? n0 : (n0 - 512);
    float acc[4][4] = {};
    gemm_tile<32,64,4,4>(g_h + (size_t)m0*HDIM, HDIM, B, ldb, HDIM, As, Bs, acc);
    const int tx = threadIdx.x & 15, ty = threadIdx.x >> 4;
    #pragma unroll
    for (int i = 0; i < 4; i++) {
        int b = m0 + ty*4 + i, c = tx*4;
        float4 p = *(const float4*)(pre + (b*TSTEPS + t)*HDIM + pc0 + c);
        float4 v = make_float4(fmaxf(acc[i][0]+p.x, 0.f), fmaxf(acc[i][1]+p.y, 0.f),
                               fmaxf(acc[i][2]+p.z, 0.f), fmaxf(acc[i][3]+p.w, 0.f));
        *(float4*)(g_hahe + b*1024 + n0 + c) = v;
    }
}

// heads: prior=ha@W_prior.T, post=he@W_post.T; softplus; rsample;
// then x[t+1] = relu(zmask @ WzzT + preAZ[t+1]). grid 4, 256 thr
__global__ __launch_bounds__(256) void k_heads(
    const float* __restrict__ W_prior, const float* __restrict__ b_prior,
    const float* __restrict__ W_post, const float* __restrict__ b_post,
    const float* __restrict__ post_noise, const float* __restrict__ dones,
    float* __restrict__ out, int t)
{
    __shared__ __align__(16) float pool[8320];
    float* Aha   = pool;          // 16*65 = 1040
    float* Ahe   = pool + 1040;   // 16*65
    float* Ws    = pool + 2080;   // 16*130 = 2080
    float* Spost = pool + 4160;   // 64*65 = 4160
    // phase-2 aliases (GEMM buffers dead by then)
    float* Wzz = pool;            // 32*64 = 2048 (over Aha+Ahe)
    float* sZ  = pool + 2080;     // 64*32 = 2048 (over Ws)

    const int m0 = blockIdx.x * 64;
    const int tid = threadIdx.x;
    const int tx = tid & 15, ty = tid >> 4;
    const int lr = tid >> 2, lk = (tid & 3) << 2;
    const int wr = tid >> 1, wk = (tid & 1) << 3;
    float acc[4][8] = {};
    const float* ApH = g_hahe + (m0 + lr)*1024 + lk;
    const float* ApE = ApH + 512;
    const float* Wrow = (wr < 64) ? (W_prior + wr*HDIM + wk) : (W_post + (wr-64)*HDIM + wk);
    for (int k0 = 0; k0 < HDIM; k0 += 16) {
        float4 a = *(const float4*)(ApH + k0);
        float4 e = *(const float4*)(ApE + k0);
        float4 w0 = *(const float4*)(Wrow + k0);
        float4 w1 = *(const float4*)(Wrow + k0 + 4);
        __syncthreads();
        Aha[(lk+0)*65+lr]=a.x; Aha[(lk+1)*65+lr]=a.y; Aha[(lk+2)*65+lr]=a.z; Aha[(lk+3)*65+lr]=a.w;
        Ahe[(lk+0)*65+lr]=e.x; Ahe[(lk+1)*65+lr]=e.y; Ahe[(lk+2)*65+lr]=e.z; Ahe[(lk+3)*65+lr]=e.w;
        Ws[(wk+0)*130+wr]=w0.x; Ws[(wk+1)*130+wr]=w0.y; Ws[(wk+2)*130+wr]=w0.z; Ws[(wk+3)*130+wr]=w0.w;
        Ws[(wk+4)*130+wr]=w1.x; Ws[(wk+5)*130+wr]=w1.y; Ws[(wk+6)*130+wr]=w1.z; Ws[(wk+7)*130+wr]=w1.w;
        __syncthreads();
        const float* Asel = (tx < 8) ? Aha : Ahe;
        #pragma unroll
        for (int kk = 0; kk < 16; kk++) {
            float av[4], bv[8];
            #pragma unroll
            for (int i = 0; i < 4; i++) av[i] = Asel[kk*65 + ty*4 + i];
            #pragma unroll
            for (int j = 0; j < 8; j++) bv[j] = Ws[kk*130 + tx*8 + j];
            #pragma unroll
            for (int i = 0; i < 4; i++)
                #pragma unroll
                for (int j = 0; j < 8; j++) acc[i][j] += av[i]*bv[j];
        }
    }
    #pragma unroll
    for (int i = 0; i < 4; i++)
        #pragma unroll
        for (int j = 0; j < 8; j++) {
            int c = tx*8 + j, r = ty*4 + i, b = m0 + r;
            if (c < 64) {
                float v = acc[i][j] + b_prior[c];
                if (c < 32) out[OFF_PM + b*TSTEPS*ZDIM + t*ZDIM + c] = v;
                else        out[OFF_PS + b*TSTEPS*ZDIM + t*ZDIM + (c-32)] = softplusf_(v);
            } else {
                Spost[r*65 + (c - 64)] = acc[i][j] + b_post[c - 64];
            }
        }
    __syncthreads();
    for (int s = tid; s < 64*ZDIM; s += 256) {
        int r = s >> 5, j = s & 31, b = m0 + r;
        float qm = Spost[r*65 + j];
        float qs = softplusf_(Spost[r*65 + 32 + j]);
        float eps = post_noise[(b*TSTEPS + t)*ZDIM + j];
        float z = qm + qs*eps;
        int o = b*TSTEPS*ZDIM + t*ZDIM + j;
        out[OFF_QM + o] = qm;
        out[OFF_QS + o] = qs;
        out[OFF_Z  + o] = z;
        if (t + 1 < TSTEPS)
            sZ[r*32 + j] = z * (1.f - dones[b*TSTEPS + t + 1]);
    }
    // phase 2: x[t+1] = relu(zmask @ WzzT + preAZ[t+1]) for rows m0..m0+63
    if (t + 1 < TSTEPS) {
        __syncthreads();
        const int col = tid & 63, rgrp = tid >> 6;
        for (int c = 0; c < 8; c++) {
            __syncthreads();
            #pragma unroll
            for (int i = 0; i < 8; i++) {
                int e = tid + i*256;
                Wzz[e] = g_WazzT[(e >> 6)*HDIM + c*64 + (e & 63)];
            }
            __syncthreads();
            #pragma unroll
            for (int rr = 0; rr < 16; rr++) {
                int r = rgrp + rr*4;
                int b = m0 + r;
                float accx = g_preAZ[(b*TSTEPS + t + 1)*HDIM + c*64 + col];
                #pragma unroll
                for (int k = 0; k < ZDIM; k++)
                    accx += sZ[r*32 + k] * Wzz[k*64 + col];
                g_x[b*HDIM + c*64 + col] = fmaxf(accx, 0.f);
            }
        }
    }
}

extern "C" void kernel_launch(void* const* d_in, const int* in_sizes, int n_in,
                              void* d_out, int out_size) {
    const float* prev_z   = (const float*)d_in[0];
    const float* prev_h   = (const float*)d_in[1];
    const float* actions  = (const float*)d_in[2];
    const float* emb      = (const float*)d_in[3];
    const float* dones    = (const float*)d_in[4];
    // d_in[5] = prior_noise (unused by reference)
    const float* post_noise = (const float*)d_in[6];
    const float* W_az = (const float*)d_in[7];
    const float* b_az = (const float*)d_in[8];
    const float* W_ih = (const float*)d_in[9];
    const float* W_hh = (const float*)d_in[10];
    const float* b_ih = (const float*)d_in[11];
    const float* b_hh = (const float*)d_in[12];
    const float* W_ha = (const float*)d_in[13];
    const float* b_ha = (const float*)d_in[14];
    const float* W_prior = (const float*)d_in[15];
    const float* b_prior = (const float*)d_in[16];
    const float* W_he = (const float*)d_in[17];
    const float* b_he = (const float*)d_in[18];
    const float* W_post = (const float*)d_in[19];
    const float* b_post = (const float*)d_in[20];
    float* out = (float*)d_out;

    k_init<<<512, 256>>>(prev_z, prev_h);
    k_pack<<<512, 256>>>(W_az, W_ha);
    k_pre_act<<<64, 256>>>(actions, W_az, b_az, W_ha, b_ha);
    k_pre_he<<<dim3(256, 8), 128>>>(emb, W_he, b_he);
    k_x<<<BATCH, 512>>>(dones, 0);

    for (int t = 0; t < TSTEPS; t++) {
        k_gates<<<dim3(4, 48), 128>>>(W_ih, W_hh, b_ih, b_hh);
        k_gru<<<512, 256>>>(out, t);
        k_hahe<<<dim3(8, 16), 128>>>(W_he, t);
        k_heads<<<4, 256>>>(W_prior, b_prior, W_post, b_post, post_noise, dones, out, t);
    }
}